// round 15
// baseline (speedup 1.0000x reference)
#include <cuda_runtime.h>
#include <cuda_bf16.h>
#include <math.h>
#include <stdint.h>

#define S_ 512
#define L_ 128

__device__ __forceinline__ float2 ffma2(float2 a, float2 b, float2 c) {
    unsigned long long ua = *reinterpret_cast<unsigned long long*>(&a);
    unsigned long long ub = *reinterpret_cast<unsigned long long*>(&b);
    unsigned long long uc = *reinterpret_cast<unsigned long long*>(&c);
    unsigned long long ud;
    asm("fma.rn.f32x2 %0, %1, %2, %3;" : "=l"(ud) : "l"(ua), "l"(ub), "l"(uc));
    return *reinterpret_cast<float2*>(&ud);
}
__device__ __forceinline__ float2 dup2(float a) {
    unsigned long long u;
    asm("mov.b64 %0, {%1, %1};" : "=l"(u) : "f"(a));
    return *reinterpret_cast<float2*>(&u);
}
__device__ __forceinline__ uint32_t bfpack(float a, float b) {
    return ((uint32_t)__bfloat16_as_ushort(__float2bfloat16_rn(b)) << 16)
         |  (uint32_t)__bfloat16_as_ushort(__float2bfloat16_rn(a));
}
__device__ __forceinline__ float bfres(float v) {
    return v - __bfloat162float(__float2bfloat16_rn(v));
}
__device__ __forceinline__ void mma16816(float* c, uint32_t a0, uint32_t a1,
                                         uint32_t a2, uint32_t a3,
                                         uint32_t b0, uint32_t b1) {
    asm volatile("mma.sync.aligned.m16n8k16.row.col.f32.bf16.bf16.f32 "
        "{%0,%1,%2,%3}, {%4,%5,%6,%7}, {%8,%9}, {%0,%1,%2,%3};"
        : "+f"(c[0]), "+f"(c[1]), "+f"(c[2]), "+f"(c[3])
        : "r"(a0), "r"(a1), "r"(a2), "r"(a3), "r"(b0), "r"(b1));
}
__device__ __forceinline__ void ldsm_x4(uint32_t& r0, uint32_t& r1,
                                        uint32_t& r2, uint32_t& r3, uint32_t addr) {
    asm volatile("ldmatrix.sync.aligned.m8n8.x4.shared.b16 {%0,%1,%2,%3}, [%4];"
        : "=r"(r0), "=r"(r1), "=r"(r2), "=r"(r3) : "r"(addr));
}

// ---- scratch ----
__device__ __align__(16) float g_xwork[(size_t)4*64*128*128];
__device__ __align__(16) uint32_t g_ub[(size_t)S_*L_*64];   // bf16x2 [row][hi32|lo32]
__device__ __align__(16) uint32_t g_wb[4*384*64];           // all 4 param sets
__device__ __align__(16) float g_zx[2][(size_t)S_*L_*384];
__device__ __align__(16) float g_dt[2][(size_t)S_*L_*4];
__device__ __align__(16) uint32_t g_gb[(size_t)S_*L_*256];  // gated bf16x2 [row][hi128|lo128]
__device__ __align__(16) uint32_t g_wcb[2*64*256];          // folded W bf16x2

// ============================================================
// Fused: LayerNorm + bf16-split pack (-> g_ub) + dt/dA (-> g_dt).
// ============================================================
__global__ __launch_bounds__(256) void ln_fused(const float* __restrict__ x_ext,
        const float* __restrict__ lnw, const float* __restrict__ lnb,
        const float* __restrict__ inW, const float* __restrict__ dtb,
        const float* __restrict__ Alog, int stage, int pf, int pb)
{
    __shared__ float tile[64][133];
    __shared__ float msh[128], rsh[128], wsh[64], bsh[64];
    __shared__ float wsm[2][2][64];
    __shared__ float par[2][2][2];
    const float* xin = stage ? g_xwork : x_ext;
    int bt = blockIdx.x, b = bt >> 7, t = bt & 127;
    int tid = threadIdx.x;
    if (tid < 64) { wsh[tid] = lnw[tid]; bsh[tid] = lnb[tid]; }
    {
        int d = tid >> 7, rest = tid & 127, h = rest >> 6, k = rest & 63;
        int pidx = d ? pb : pf;
        wsm[d][h][k] = inW[(size_t)pidx*386*64 + (384 + h)*64 + k];
    }
    if (tid < 4) {
        int d = tid >> 1, h = tid & 1;
        int pidx = d ? pb : pf;
        par[d][h][0] = dtb[pidx*2 + h];
        par[d][h][1] = -expf(Alog[pidx*2 + h]);
    }
    const float* xb = xin + ((size_t)b*64*128 + t)*128;
    for (int i = tid; i < 8192; i += 256) {
        int c = i >> 7, f = i & 127;
        tile[c][f] = xb[(size_t)c*16384 + f];
    }
    __syncthreads();
    if (tid < 128) {
        float s = 0.f, ss = 0.f;
        #pragma unroll
        for (int c = 0; c < 64; c++) { float v = tile[c][tid]; s += v; ss += v*v; }
        float m = s * 0.015625f;
        msh[tid] = m;
        rsh[tid] = rsqrtf(ss * 0.015625f - m*m + 1e-5f);
    }
    __syncthreads();
    for (int i = tid; i < 8192; i += 256) {
        int c = i >> 7, f = i & 127;
        tile[c][f] = (tile[c][f] - msh[f]) * rsh[f] * wsh[c] + bsh[c];
    }
    __syncthreads();
    {
        int w = tid & 31, fb_ = tid >> 5;
        #pragma unroll
        for (int k = 0; k < 16; k++) {
            int f = fb_ + k*8;
            float a = tile[2*w][f], c2 = tile[2*w + 1][f];
            int row = stage ? ((b << 7) + f)*128 + t : ((b << 7) + t)*128 + f;
            uint32_t* o = g_ub + (size_t)row*64;
            o[w]      = bfpack(a, c2);
            o[32 + w] = bfpack(bfres(a), bfres(c2));
        }
    }
    {
        int f = tid >> 1, d = tid & 1;
        float a0 = 0.f, a1 = 0.f;
        #pragma unroll
        for (int c = 0; c < 64; c++) {
            float v = tile[c][f];
            a0 = fmaf(v, wsm[d][0][c], a0);
            a1 = fmaf(v, wsm[d][1][c], a1);
        }
        float xr0 = a0 + par[d][0][0];
        float xr1 = a1 + par[d][1][0];
        float dt0 = (xr0 > 20.f) ? xr0 : log1pf(expf(xr0));
        float dt1 = (xr1 > 20.f) ? xr1 : log1pf(expf(xr1));
        int row = stage ? ((b << 7) + f)*128 + t : ((b << 7) + t)*128 + f;
        *(float4*)&g_dt[d][(size_t)row*4] =
            make_float4(dt0, dt1, par[d][0][1]*dt0, par[d][1][1]*dt1);
    }
}

// ============================================================
// weight bf16-split conversion, ALL 4 param sets in one launch
// ============================================================
__global__ __launch_bounds__(256) void w_conv_all(const float* __restrict__ inW)
{
    int idx = blockIdx.x*256 + threadIdx.x;
    int p = idx / 6144, r = idx - p*6144;
    int n = r >> 4, wq = r & 15;
    float4 v = *(const float4*)&inW[(size_t)p*386*64 + n*64 + wq*4];
    uint32_t* o = g_wb + (size_t)(p*384 + n)*64;
    int wo = wq*2;
    *(uint2*)&o[wo]      = make_uint2(bfpack(v.x, v.y), bfpack(v.z, v.w));
    *(uint2*)&o[32 + wo] = make_uint2(bfpack(bfres(v.x), bfres(v.y)),
                                      bfpack(bfres(v.z), bfres(v.w)));
}

// ============================================================
// in_proj via tensor cores (bf16-split, 3 passes) — R14 tiling,
// operand loads upgraded to ldmatrix (288 LDS.32 -> 72 LDSM.x4).
// ============================================================
#define GIN_SMEM_BYTES (2*128*68*4)
__global__ __launch_bounds__(256, 2) void gemm_in_mma(int st)
{
    extern __shared__ uint32_t smw[];
    uint32_t* Asm = smw;
    uint32_t* Bsm = smw + 128*68;
    int bx = blockIdx.x;
    int dir = (bx >= 3);
    int j0 = (bx - dir*3) * 128;
    size_t bm = (size_t)blockIdx.y * 128;
    int tid = threadIdx.x;

    const uint4* gu = (const uint4*)&g_ub[bm*64];
    const uint4* gw = (const uint4*)&g_wb[(size_t)((st*2 + dir)*384 + j0)*64];
    #pragma unroll
    for (int t = 0; t < 8; t++) {
        int i = tid + t*256;
        int row = i >> 4, wq = i & 15;
        *(uint4*)&Asm[row*68 + wq*4] = gu[i];
        *(uint4*)&Bsm[row*68 + wq*4] = gw[i];
    }
    __syncthreads();

    int wid = tid >> 5, lane = tid & 31;
    int wm = wid & 3, wn = wid >> 2;
    int q = lane >> 2, w = lane & 3;

    // ldmatrix per-lane base addresses (byte, shared space)
    uint32_t sA = (uint32_t)__cvta_generic_to_shared(Asm);
    uint32_t sB = (uint32_t)__cvta_generic_to_shared(Bsm);
    int rlow = lane & 15;          // row within 16-row piece-pair
    int khalf = (lane >> 4) << 2;  // +4 words for k8-15 pieces
    uint32_t aAddr0 = sA + (((wm*32 + rlow)*68 + khalf) << 2);
    uint32_t aAddr1 = aAddr0 + (16*68 << 2);
    int r_in = lane & 7;
    int piece = lane >> 3;          // 0..3
    int bro = ((piece >> 1) << 3) + r_in;       // +8 rows for pieces 2,3
    int bko = (piece & 1) << 2;                 // +4 words for odd pieces
    uint32_t bAddr = sB + (((wn*64 + bro)*68 + bko) << 2);

    float acc[2][8][4];
    #pragma unroll
    for (int mh = 0; mh < 2; mh++)
        #pragma unroll
        for (int tn = 0; tn < 8; tn++)
            #pragma unroll
            for (int r = 0; r < 4; r++) acc[mh][tn][r] = 0.f;

    #pragma unroll
    for (int c = 0; c < 3; c++) {
        int aoff = (c == 2) ? 32 : 0;
        int boff = (c == 1) ? 32 : 0;
        #pragma unroll
        for (int kc = 0; kc < 4; kc++) {
            uint32_t a0, a1, a2, a3, a4, a5, a6, a7;
            ldsm_x4(a0, a1, a2, a3, aAddr0 + ((aoff + kc*8) << 2));
            ldsm_x4(a4, a5, a6, a7, aAddr1 + ((aoff + kc*8) << 2));
            #pragma unroll
            for (int tp = 0; tp < 4; tp++) {
                uint32_t b0a, b1a, b0b, b1b;
                ldsm_x4(b0a, b1a, b0b, b1b,
                        bAddr + ((boff + kc*8) << 2) + ((tp*16*68) << 2));
                int tn = tp*2;
                mma16816(acc[0][tn],   a0, a1, a2, a3, b0a, b1a);
                mma16816(acc[1][tn],   a4, a5, a6, a7, b0a, b1a);
                mma16816(acc[0][tn+1], a0, a1, a2, a3, b0b, b1b);
                mma16816(acc[1][tn+1], a4, a5, a6, a7, b0b, b1b);
            }
        }
    }

    float* Cout = g_zx[dir];
    #pragma unroll
    for (int mh = 0; mh < 2; mh++) {
        #pragma unroll
        for (int tn = 0; tn < 8; tn++) {
            size_t m0 = bm + wm*32 + mh*16 + q;
            int col = j0 + wn*64 + tn*8 + w*2;
            *(float2*)&Cout[m0*384 + col] =
                make_float2(acc[mh][tn][0], acc[mh][tn][1]);
            *(float2*)&Cout[(m0+8)*384 + col] =
                make_float2(acc[mh][tn][2], acc[mh][tn][3]);
        }
    }
}

// ============================================================
// Fused SSD (R5-exact compute; epilogue emits bf16 hi/lo)
// ============================================================
#define SMX 0
#define SMBT 16896
#define SMCT 25344
#define SMG 33792
#define SMLL 50688
#define SMDT 50944
#define SSD_SMEM_FLOATS 51200
#define SSD_SMEM_BYTES (SSD_SMEM_FLOATS*4)

__global__ __launch_bounds__(512, 1) void ssd_kernel(
    const float* __restrict__ convW, const float* __restrict__ convB,
    const float* __restrict__ Dp, const float* __restrict__ normw, int pf, int pb)
{
    extern __shared__ float sm[];
    int blk = blockIdx.x, dir = blk >> 9, s = blk & 511;
    int pidx = dir ? pb : pf;
    int tid = threadIdx.x;
    const float* zxa = g_zx[dir] + (size_t)s * L_ * 384;

    {
        int ch = tid & 255, hf = tid >> 8;
        float cw0 = convW[pidx*1024 + ch*4 + 0];
        float cw1 = convW[pidx*1024 + ch*4 + 1];
        float cw2 = convW[pidx*1024 + ch*4 + 2];
        float cw3 = convW[pidx*1024 + ch*4 + 3];
        float cb  = convB[pidx*256 + ch];
        const float* src = zxa + 128 + ch;
        float* obase;
        int ostep;
        if (ch < 128)      { obase = sm + SMX + ch;              ostep = 132; }
        else if (ch < 192) { obase = sm + SMBT + (ch-128)*132;   ostep = 1;   }
        else               { obase = sm + SMCT + (ch-192)*132;   ostep = 1;   }
        int ls = hf * 64;
        float xm3 = 0.f, xm2 = 0.f, xm1 = 0.f;
        #pragma unroll
        for (int j = 0; j < 3; j++) {
            int l = ls - 3 + j;
            float v = 0.f;
            if (l >= 0) v = src[(size_t)(dir ? 127-l : l)*384];
            xm3 = xm2; xm2 = xm1; xm1 = v;
        }
        float nxt[4];
        #pragma unroll
        for (int j = 0; j < 4; j++)
            nxt[j] = src[(size_t)(dir ? 127-(ls+j) : (ls+j))*384];
        for (int lb = 0; lb < 64; lb += 4) {
            float cur[4];
            #pragma unroll
            for (int j = 0; j < 4; j++) cur[j] = nxt[j];
            if (lb + 4 < 64) {
                #pragma unroll
                for (int j = 0; j < 4; j++) {
                    int l = ls + lb + 4 + j;
                    nxt[j] = src[(size_t)(dir ? 127-l : l)*384];
                }
            }
            #pragma unroll
            for (int j = 0; j < 4; j++) {
                float v = cur[j];
                float acc = cb;
                acc = fmaf(cw0, xm3, acc);
                acc = fmaf(cw1, xm2, acc);
                acc = fmaf(cw2, xm1, acc);
                acc = fmaf(cw3, v,   acc);
                xm3 = xm2; xm2 = xm1; xm1 = v;
                float y = acc / (1.f + expf(-acc));
                obase[(ls + lb + j) * ostep] = y;
            }
        }
    }
    if (tid < 64) {
        int h = tid >> 5, lane = tid & 31;
        float carry = 0.f;
        for (int c = 0; c < 4; c++) {
            int l = c*32 + lane;
            int lp = dir ? 127 - l : l;
            const float* dr = g_dt[dir] + ((size_t)s*128 + lp)*4;
            sm[SMDT + h*128 + l] = dr[h];
            float v = dr[2 + h];
            #pragma unroll
            for (int o = 1; o < 32; o <<= 1) {
                float t = __shfl_up_sync(0xffffffffu, v, o);
                if (lane >= o) v += t;
            }
            sm[SMLL + h*128 + l] = v + carry;
            carry += __shfl_sync(0xffffffffu, v, 31);
        }
    }
    __syncthreads();

    int ti = tid >> 4;
    int pi = tid & 15;
    int t0 = ti * 4;
    float2 accY[2][4][2];
    #pragma unroll
    for (int h = 0; h < 2; h++)
        #pragma unroll
        for (int i = 0; i < 4; i++) {
            accY[h][i][0] = make_float2(0.f, 0.f);
            accY[h][i][1] = make_float2(0.f, 0.f);
        }

    #pragma unroll
    for (int p = 0; p < 2; p++) {
        int s_base = p * 64;
        int s0 = s_base + pi * 4;
        float2 pacc[4][2];
        #pragma unroll
        for (int i = 0; i < 4; i++) {
            pacc[i][0] = make_float2(0.f, 0.f);
            pacc[i][1] = make_float2(0.f, 0.f);
        }
        if (s0 <= t0 + 3) {
            #pragma unroll 4
            for (int n = 0; n < 64; n++) {
                float4 c4 = *(const float4*)&sm[SMCT + n*132 + t0];
                float4 b4 = *(const float4*)&sm[SMBT + n*132 + s0];
                float a[4] = {c4.x, c4.y, c4.z, c4.w};
                float2 bb[2] = {{b4.x, b4.y}, {b4.z, b4.w}};
                #pragma unroll
                for (int i = 0; i < 4; i++) {
                    float2 aa = dup2(a[i]);
                    pacc[i][0] = ffma2(aa, bb[0], pacc[i][0]);
                    pacc[i][1] = ffma2(aa, bb[1], pacc[i][1]);
                }
            }
        }
        #pragma unroll
        for (int h = 0; h < 2; h++) {
            float llt[4];
            #pragma unroll
            for (int i = 0; i < 4; i++) llt[i] = sm[SMLL + h*128 + t0 + i];
            #pragma unroll
            for (int j = 0; j < 4; j++) {
                int sg = s0 + j;
                float dts = sm[SMDT + h*128 + sg];
                float lls = sm[SMLL + h*128 + sg];
                float pv[4];
                #pragma unroll
                for (int i = 0; i < 4; i++)
                    pv[i] = (j & 1) ? pacc[i][j>>1].y : pacc[i][j>>1].x;
                float4 g4;
                g4.x = (sg <= t0+0) ? pv[0]*dts*__expf(llt[0]-lls) : 0.f;
                g4.y = (sg <= t0+1) ? pv[1]*dts*__expf(llt[1]-lls) : 0.f;
                g4.z = (sg <= t0+2) ? pv[2]*dts*__expf(llt[2]-lls) : 0.f;
                g4.w = (sg <= t0+3) ? pv[3]*dts*__expf(llt[3]-lls) : 0.f;
                *(float4*)&sm[SMG + (h*64 + sg - s_base)*132 + t0] = g4;
            }
        }
        __syncthreads();
        int klim = t0 + 4 - s_base;
        if (klim > 64) klim = 64;
        for (int sl = 0; sl < klim; sl++) {
            int sg = s_base + sl;
            float4 g0 = *(const float4*)&sm[SMG + sl*132 + t0];
            float4 g1 = *(const float4*)&sm[SMG + (64 + sl)*132 + t0];
            float4 x0 = *(const float4*)&sm[SMX + sg*132 + pi*4];
            float4 x1 = *(const float4*)&sm[SMX + sg*132 + 64 + pi*4];
            float2 b00 = {x0.x, x0.y}, b01 = {x0.z, x0.w};
            float2 b10 = {x1.x, x1.y}, b11 = {x1.z, x1.w};
            float ga0[4] = {g0.x, g0.y, g0.z, g0.w};
            float ga1[4] = {g1.x, g1.y, g1.z, g1.w};
            #pragma unroll
            for (int i = 0; i < 4; i++) {
                float2 a0 = dup2(ga0[i]);
                float2 a1 = dup2(ga1[i]);
                accY[0][i][0] = ffma2(a0, b00, accY[0][i][0]);
                accY[0][i][1] = ffma2(a0, b01, accY[0][i][1]);
                accY[1][i][0] = ffma2(a1, b10, accY[1][i][0]);
                accY[1][i][1] = ffma2(a1, b11, accY[1][i][1]);
            }
        }
        __syncthreads();
    }

    {
        float Dv0 = Dp[pidx*2], Dv1 = Dp[pidx*2 + 1];
        float4 nw0 = *(const float4*)&normw[pidx*128 + pi*4];
        float4 nw1 = *(const float4*)&normw[pidx*128 + 64 + pi*4];
        #pragma unroll
        for (int i = 0; i < 4; i++) {
            int l = t0 + i;
            int lp = dir ? 127 - l : l;
            float4 x0 = *(const float4*)&sm[SMX + l*132 + pi*4];
            float4 x1 = *(const float4*)&sm[SMX + l*132 + 64 + pi*4];
            const float* zr = zxa + (size_t)lp*384;
            float4 z0 = *(const float4*)&zr[pi*4];
            float4 z1 = *(const float4*)&zr[64 + pi*4];
            float g[8];
            g[0] = fmaf(Dv0, x0.x, accY[0][i][0].x);
            g[1] = fmaf(Dv0, x0.y, accY[0][i][0].y);
            g[2] = fmaf(Dv0, x0.z, accY[0][i][1].x);
            g[3] = fmaf(Dv0, x0.w, accY[0][i][1].y);
            g[4] = fmaf(Dv1, x1.x, accY[1][i][0].x);
            g[5] = fmaf(Dv1, x1.y, accY[1][i][0].y);
            g[6] = fmaf(Dv1, x1.z, accY[1][i][1].x);
            g[7] = fmaf(Dv1, x1.w, accY[1][i][1].y);
            float z[8] = {z0.x, z0.y, z0.z, z0.w, z1.x, z1.y, z1.z, z1.w};
            float ss = 0.f;
            #pragma unroll
            for (int j = 0; j < 8; j++) {
                g[j] = g[j] * (z[j] / (1.f + expf(-z[j])));
                ss = fmaf(g[j], g[j], ss);
            }
            ss += __shfl_xor_sync(0xffffffffu, ss, 1);
            ss += __shfl_xor_sync(0xffffffffu, ss, 2);
            ss += __shfl_xor_sync(0xffffffffu, ss, 4);
            ss += __shfl_xor_sync(0xffffffffu, ss, 8);
            float rs = rsqrtf(ss * 0.0078125f + 1e-5f);
            float o0 = g[0]*rs*nw0.x, o1 = g[1]*rs*nw0.y;
            float o2 = g[2]*rs*nw0.z, o3 = g[3]*rs*nw0.w;
            float o4 = g[4]*rs*nw1.x, o5 = g[5]*rs*nw1.y;
            float o6 = g[6]*rs*nw1.z, o7 = g[7]*rs*nw1.w;
            uint32_t* go = g_gb + ((size_t)s*128 + lp)*256;
            int w0 = (dir << 6) + pi*2;
            *(uint2*)&go[w0]          = make_uint2(bfpack(o0, o1), bfpack(o2, o3));
            *(uint2*)&go[w0 + 32]     = make_uint2(bfpack(o4, o5), bfpack(o6, o7));
            *(uint2*)&go[128 + w0]    = make_uint2(bfpack(bfres(o0), bfres(o1)),
                                                   bfpack(bfres(o2), bfres(o3)));
            *(uint2*)&go[128 + w0+32] = make_uint2(bfpack(bfres(o4), bfres(o5)),
                                                   bfpack(bfres(o6), bfres(o7)));
        }
    }
}

// ============================================================
// Fold out_proj x fusion — both stages, packed bf16 hi/lo
// ============================================================
__global__ void wc_all(const float* __restrict__ fW, const float* __restrict__ oW)
{
    int idx = blockIdx.x*256 + threadIdx.x;
    int st = idx >> 14, r = idx & 16383;
    int m = r >> 8, rr = r & 255, dir = rr >> 7, j = rr & 127;
    int pidx = st*2 + dir;
    const float* wo = oW + (size_t)pidx*64*128;
    const float* wf = fW + st*64*128 + m*128 + (dir << 6);
    float acc = 0.f;
    #pragma unroll
    for (int i = 0; i < 64; i++) acc = fmaf(wf[i], wo[i*128 + j], acc);
    float part = __shfl_xor_sync(0xffffffffu, acc, 1);
    if (!(rr & 1)) {
        int kw = rr >> 1;
        uint32_t* o = g_wcb + (size_t)(st*64 + m)*256;
        o[kw]       = bfpack(acc, part);
        o[128 + kw] = bfpack(bfres(acc), bfres(part));
    }
}

// ============================================================
// final GEMM via tensor cores (R14-exact) + residual
// ============================================================
#define GOUT_SMEM_BYTES ((128*132 + 64*132)*4)
__global__ __launch_bounds__(256, 2) void gemm_out_mma(const float* __restrict__ fb,
        const float* __restrict__ x_ext, float* __restrict__ out_ext, int stage)
{
    extern __shared__ uint32_t smo[];
    uint32_t* Asm = smo;
    uint32_t* Bsm = smo + 128*132;
    const float* xin = stage ? g_xwork : x_ext;
    float* xout = stage ? out_ext : g_xwork;
    int blk = blockIdx.x;
    int b = blk >> 7, tt = blk & 127;
    int tid = threadIdx.x;
    int rbase = b*16384 + (stage ? tt : tt*128);
    int rstep = stage ? 128 : 1;

    int wid = tid >> 5, lane = tid & 31;
    int wm = wid & 3, wn = wid >> 2;
    int q = lane >> 2, w = lane & 3;
    uint32_t a_row = (wm*32 + q)*132;
    uint32_t b_row = (wn*32 + q)*132;

    float acc[2][4][4];
    #pragma unroll
    for (int mh = 0; mh < 2; mh++)
        #pragma unroll
        for (int tn = 0; tn < 4; tn++)
            #pragma unroll
            for (int r = 0; r < 4; r++) acc[mh][tn][r] = 0.f;

    for (int half = 0; half < 2; half++) {
        if (half) __syncthreads();
        #pragma unroll
        for (int t = 0; t < 16; t++) {
            int i = tid + t*256;
            int row = i >> 5, wq = i & 31;
            const uint32_t* src = g_gb + (size_t)(rbase + row*rstep)*256;
            int so, dof;
            if (wq < 16) { so = half*64 + wq*4;              dof = wq*4; }
            else         { so = 128 + half*64 + (wq-16)*4;   dof = 64 + (wq-16)*4; }
            *(uint4*)&Asm[row*132 + dof] = *(const uint4*)&src[so];
        }
        #pragma unroll
        for (int t = 0; t < 8; t++) {
            int i = tid + t*256;
            int row = i >> 5, wq = i & 31;
            const uint32_t* src = g_wcb + (size_t)(stage*64 + row)*256;
            int so, dof;
            if (wq < 16) { so = half*64 + wq*4;              dof = wq*4; }
            else         { so = 128 + half*64 + (wq-16)*4;   dof = 64 + (wq-16)*4; }
            *(uint4*)&Bsm[row*132 + dof] = *(const uint4*)&src[so];
        }
        __syncthreads();
        #pragma unroll
        for (int c = 0; c < 3; c++) {
            int aoff = (c == 2) ? 64 : 0;
            int boff = (c == 1) ? 64 : 0;
            #pragma unroll
            for (int kc = 0; kc < 8; kc++) {
                int kb = kc*8 + w;
                uint32_t a0 = Asm[a_row + aoff + kb];
                uint32_t a1 = Asm[a_row + 8*132 + aoff + kb];
                uint32_t a2 = Asm[a_row + aoff + kb + 4];
                uint32_t a3 = Asm[a_row + 8*132 + aoff + kb + 4];
                uint32_t a4 = Asm[a_row + 16*132 + aoff + kb];
                uint32_t a5 = Asm[a_row + 24*132 + aoff + kb];
                uint32_t a6 = Asm[a_row + 16*132 + aoff + kb + 4];
                uint32_t a7 = Asm[a_row + 24*132 + aoff + kb + 4];
                #pragma unroll
                for (int tn = 0; tn < 4; tn++) {
                    uint32_t b0 = Bsm[b_row + tn*8*132 + boff + kb];
                    uint32_t b1 = Bsm[b_row + tn*8*132 + boff + kb + 4];
                    mma16816(acc[0][tn], a0, a1, a2, a3, b0, b1);
                    mma16816(acc[1][tn], a4, a5, a6, a7, b0, b1);
                }
            }
        }
    }
    __syncthreads();
    float* Cs = (float*)smo;
    #pragma unroll
    for (int mh = 0; mh < 2; mh++)
        #pragma unroll
        for (int tn = 0; tn < 4; tn++) {
            int ml = wm*32 + mh*16 + q;
            int col = wn*32 + tn*8 + w*2;
            Cs[col*132 + ml]           = acc[mh][tn][0];
            Cs[(col+1)*132 + ml]       = acc[mh][tn][1];
            Cs[col*132 + ml + 8]       = acc[mh][tn][2];
            Cs[(col+1)*132 + ml + 8]   = acc[mh][tn][3];
        }
    __syncthreads();
    int fq = tid & 31, ng = tid >> 5;
    #pragma unroll
    for (int nn = 0; nn < 8; nn++) {
        int n = ng + nn*8;
        float fbv = fb[n];
        size_t base = (((size_t)(b*64 + n)*128) + tt)*128 + fq*4;
        float4 xv = *(const float4*)&xin[base];
        const float* cr = Cs + n*132 + fq*4;
        float4 o;
        o.x = xv.x + cr[0] + fbv;
        o.y = xv.y + cr[1] + fbv;
        o.z = xv.z + cr[2] + fbv;
        o.w = xv.w + cr[3] + fbv;
        *(float4*)&xout[base] = o;
    }
}

// ============================================================
extern "C" void kernel_launch(void* const* d_in, const int* in_sizes, int n_in,
                              void* d_out, int out_size)
{
    const float* x     = (const float*)d_in[0];
    const float* inW   = (const float*)d_in[1];
    const float* convW = (const float*)d_in[2];
    const float* convB = (const float*)d_in[3];
    const float* dtb   = (const float*)d_in[4];
    const float* Alog  = (const float*)d_in[5];
    const float* Dp    = (const float*)d_in[6];
    const float* nw    = (const float*)d_in[7];
    const float* outW  = (const float*)d_in[8];
    const float* fW    = (const float*)d_in[9];
    const float* fb    = (const float*)d_in[10];
    const float* lnw   = (const float*)d_in[11];
    const float* lnb   = (const float*)d_in[12];
    float* out = (float*)d_out;

    cudaFuncSetAttribute(gemm_in_mma, cudaFuncAttributeMaxDynamicSharedMemorySize,
                         GIN_SMEM_BYTES);
    cudaFuncSetAttribute(ssd_kernel, cudaFuncAttributeMaxDynamicSharedMemorySize,
                         SSD_SMEM_BYTES);
    cudaFuncSetAttribute(gemm_out_mma, cudaFuncAttributeMaxDynamicSharedMemorySize,
                         GOUT_SMEM_BYTES);

    // stage-invariant prep
    w_conv_all<<<96, 256>>>(inW);
    wc_all<<<128, 256>>>(fW, outW);

    for (int st = 0; st < 2; st++) {
        int pf = 2*st, pb = 2*st + 1;
        ln_fused<<<512, 256>>>(x, lnw + st*64, lnb + st*64, inW, dtb, Alog,
                               st, pf, pb);
        gemm_in_mma<<<dim3(6, 512), 256, GIN_SMEM_BYTES>>>(st);
        ssd_kernel<<<1024, 512, SSD_SMEM_BYTES>>>(convW, convB, Dp, nw, pf, pb);
        gemm_out_mma<<<512, 256, GOUT_SMEM_BYTES>>>(fb + st*64, x, out, st);
    }
}

// round 16
// speedup vs baseline: 1.1203x; 1.1203x over previous
#include <cuda_runtime.h>
#include <cuda_bf16.h>
#include <math.h>
#include <stdint.h>

#define S_ 512
#define L_ 128

__device__ __forceinline__ float2 ffma2(float2 a, float2 b, float2 c) {
    unsigned long long ua = *reinterpret_cast<unsigned long long*>(&a);
    unsigned long long ub = *reinterpret_cast<unsigned long long*>(&b);
    unsigned long long uc = *reinterpret_cast<unsigned long long*>(&c);
    unsigned long long ud;
    asm("fma.rn.f32x2 %0, %1, %2, %3;" : "=l"(ud) : "l"(ua), "l"(ub), "l"(uc));
    return *reinterpret_cast<float2*>(&ud);
}
__device__ __forceinline__ float2 dup2(float a) {
    unsigned long long u;
    asm("mov.b64 %0, {%1, %1};" : "=l"(u) : "f"(a));
    return *reinterpret_cast<float2*>(&u);
}
__device__ __forceinline__ uint32_t bfpack(float a, float b) {
    return ((uint32_t)__bfloat16_as_ushort(__float2bfloat16_rn(b)) << 16)
         |  (uint32_t)__bfloat16_as_ushort(__float2bfloat16_rn(a));
}
__device__ __forceinline__ float bfres(float v) {
    return v - __bfloat162float(__float2bfloat16_rn(v));
}
__device__ __forceinline__ float sigmoid_t(float x) {
    float t;
    asm("tanh.approx.f32 %0, %1;" : "=f"(t) : "f"(0.5f * x));
    return fmaf(0.5f, t, 0.5f);
}
__device__ __forceinline__ void mma16816(float* c, uint32_t a0, uint32_t a1,
                                         uint32_t a2, uint32_t a3,
                                         uint32_t b0, uint32_t b1) {
    asm volatile("mma.sync.aligned.m16n8k16.row.col.f32.bf16.bf16.f32 "
        "{%0,%1,%2,%3}, {%4,%5,%6,%7}, {%8,%9}, {%0,%1,%2,%3};"
        : "+f"(c[0]), "+f"(c[1]), "+f"(c[2]), "+f"(c[3])
        : "r"(a0), "r"(a1), "r"(a2), "r"(a3), "r"(b0), "r"(b1));
}

// ---- scratch ----
__device__ __align__(16) float g_xwork[(size_t)4*64*128*128];
__device__ __align__(16) uint32_t g_ub[(size_t)S_*L_*64];   // bf16x2 [row][hi32|lo32]
__device__ __align__(16) uint32_t g_wb[4*384*64];           // all 4 param sets
__device__ __align__(16) float g_zx[2][(size_t)S_*L_*384];
__device__ __align__(16) float g_dt[2][(size_t)S_*L_*4];
__device__ __align__(16) uint32_t g_gb[(size_t)S_*L_*256];  // gated bf16x2 [row][hi128|lo128]
__device__ __align__(16) uint32_t g_wcb[2*64*256];          // folded W bf16x2

// ============================================================
// Fused: LayerNorm + bf16-split pack (-> g_ub) + dt/dA (-> g_dt).
// ============================================================
__global__ __launch_bounds__(256) void ln_fused(const float* __restrict__ x_ext,
        const float* __restrict__ lnw, const float* __restrict__ lnb,
        const float* __restrict__ inW, const float* __restrict__ dtb,
        const float* __restrict__ Alog, int stage, int pf, int pb)
{
    __shared__ float tile[64][133];
    __shared__ float msh[128], rsh[128], wsh[64], bsh[64];
    __shared__ float wsm[2][2][64];
    __shared__ float par[2][2][2];
    const float* xin = stage ? g_xwork : x_ext;
    int bt = blockIdx.x, b = bt >> 7, t = bt & 127;
    int tid = threadIdx.x;
    if (tid < 64) { wsh[tid] = lnw[tid]; bsh[tid] = lnb[tid]; }
    {
        int d = tid >> 7, rest = tid & 127, h = rest >> 6, k = rest & 63;
        int pidx = d ? pb : pf;
        wsm[d][h][k] = inW[(size_t)pidx*386*64 + (384 + h)*64 + k];
    }
    if (tid < 4) {
        int d = tid >> 1, h = tid & 1;
        int pidx = d ? pb : pf;
        par[d][h][0] = dtb[pidx*2 + h];
        par[d][h][1] = -expf(Alog[pidx*2 + h]);
    }
    const float* xb = xin + ((size_t)b*64*128 + t)*128;
    for (int i = tid; i < 8192; i += 256) {
        int c = i >> 7, f = i & 127;
        tile[c][f] = xb[(size_t)c*16384 + f];
    }
    __syncthreads();
    if (tid < 128) {
        float s = 0.f, ss = 0.f;
        #pragma unroll
        for (int c = 0; c < 64; c++) { float v = tile[c][tid]; s += v; ss += v*v; }
        float m = s * 0.015625f;
        msh[tid] = m;
        rsh[tid] = rsqrtf(ss * 0.015625f - m*m + 1e-5f);
    }
    __syncthreads();
    for (int i = tid; i < 8192; i += 256) {
        int c = i >> 7, f = i & 127;
        tile[c][f] = (tile[c][f] - msh[f]) * rsh[f] * wsh[c] + bsh[c];
    }
    __syncthreads();
    {
        int w = tid & 31, fb_ = tid >> 5;
        #pragma unroll
        for (int k = 0; k < 16; k++) {
            int f = fb_ + k*8;
            float a = tile[2*w][f], c2 = tile[2*w + 1][f];
            int row = stage ? ((b << 7) + f)*128 + t : ((b << 7) + t)*128 + f;
            uint32_t* o = g_ub + (size_t)row*64;
            o[w]      = bfpack(a, c2);
            o[32 + w] = bfpack(bfres(a), bfres(c2));
        }
    }
    {
        int f = tid >> 1, d = tid & 1;
        float a0 = 0.f, a1 = 0.f;
        #pragma unroll
        for (int c = 0; c < 64; c++) {
            float v = tile[c][f];
            a0 = fmaf(v, wsm[d][0][c], a0);
            a1 = fmaf(v, wsm[d][1][c], a1);
        }
        float xr0 = a0 + par[d][0][0];
        float xr1 = a1 + par[d][1][0];
        float dt0 = (xr0 > 20.f) ? xr0 : log1pf(expf(xr0));
        float dt1 = (xr1 > 20.f) ? xr1 : log1pf(expf(xr1));
        int row = stage ? ((b << 7) + f)*128 + t : ((b << 7) + t)*128 + f;
        *(float4*)&g_dt[d][(size_t)row*4] =
            make_float4(dt0, dt1, par[d][0][1]*dt0, par[d][1][1]*dt1);
    }
}

// ============================================================
// weight bf16-split conversion, ALL 4 param sets in one launch
// ============================================================
__global__ __launch_bounds__(256) void w_conv_all(const float* __restrict__ inW)
{
    int idx = blockIdx.x*256 + threadIdx.x;
    int p = idx / 6144, r = idx - p*6144;
    int n = r >> 4, wq = r & 15;
    float4 v = *(const float4*)&inW[(size_t)p*386*64 + n*64 + wq*4];
    uint32_t* o = g_wb + (size_t)(p*384 + n)*64;
    int wo = wq*2;
    *(uint2*)&o[wo]      = make_uint2(bfpack(v.x, v.y), bfpack(v.z, v.w));
    *(uint2*)&o[32 + wo] = make_uint2(bfpack(bfres(v.x), bfres(v.y)),
                                      bfpack(bfres(v.z), bfres(v.w)));
}

// ============================================================
// in_proj via tensor cores (bf16-split, 3 passes) — R14-exact
// ============================================================
#define GIN_SMEM_BYTES (2*128*68*4)
__global__ __launch_bounds__(256, 2) void gemm_in_mma(int st)
{
    extern __shared__ uint32_t smw[];
    uint32_t* Asm = smw;
    uint32_t* Bsm = smw + 128*68;
    int bx = blockIdx.x;
    int dir = (bx >= 3);
    int j0 = (bx - dir*3) * 128;
    size_t bm = (size_t)blockIdx.y * 128;
    int tid = threadIdx.x;

    const uint4* gu = (const uint4*)&g_ub[bm*64];
    const uint4* gw = (const uint4*)&g_wb[(size_t)((st*2 + dir)*384 + j0)*64];
    #pragma unroll
    for (int t = 0; t < 8; t++) {
        int i = tid + t*256;
        int row = i >> 4, wq = i & 15;
        *(uint4*)&Asm[row*68 + wq*4] = gu[i];
        *(uint4*)&Bsm[row*68 + wq*4] = gw[i];
    }
    __syncthreads();

    int wid = tid >> 5, lane = tid & 31;
    int wm = wid & 3, wn = wid >> 2;
    int q = lane >> 2, w = lane & 3;
    uint32_t a_row = (wm*32 + q)*68;
    uint32_t b_row = (wn*64 + q)*68;

    float acc[2][8][4];
    #pragma unroll
    for (int mh = 0; mh < 2; mh++)
        #pragma unroll
        for (int tn = 0; tn < 8; tn++)
            #pragma unroll
            for (int r = 0; r < 4; r++) acc[mh][tn][r] = 0.f;

    #pragma unroll
    for (int c = 0; c < 3; c++) {
        int aoff = (c == 2) ? 32 : 0;
        int boff = (c == 1) ? 32 : 0;
        #pragma unroll
        for (int kc = 0; kc < 4; kc++) {
            int kb = kc*8 + w;
            uint32_t a0 = Asm[a_row + aoff + kb];
            uint32_t a1 = Asm[a_row + 8*68 + aoff + kb];
            uint32_t a2 = Asm[a_row + aoff + kb + 4];
            uint32_t a3 = Asm[a_row + 8*68 + aoff + kb + 4];
            uint32_t a4 = Asm[a_row + 16*68 + aoff + kb];
            uint32_t a5 = Asm[a_row + 24*68 + aoff + kb];
            uint32_t a6 = Asm[a_row + 16*68 + aoff + kb + 4];
            uint32_t a7 = Asm[a_row + 24*68 + aoff + kb + 4];
            #pragma unroll
            for (int tn = 0; tn < 8; tn++) {
                uint32_t b0 = Bsm[b_row + tn*8*68 + boff + kb];
                uint32_t b1 = Bsm[b_row + tn*8*68 + boff + kb + 4];
                mma16816(acc[0][tn], a0, a1, a2, a3, b0, b1);
                mma16816(acc[1][tn], a4, a5, a6, a7, b0, b1);
            }
        }
    }

    float* Cout = g_zx[dir];
    #pragma unroll
    for (int mh = 0; mh < 2; mh++) {
        #pragma unroll
        for (int tn = 0; tn < 8; tn++) {
            size_t m0 = bm + wm*32 + mh*16 + q;
            int col = j0 + wn*64 + tn*8 + w*2;
            *(float2*)&Cout[m0*384 + col] =
                make_float2(acc[mh][tn][0], acc[mh][tn][1]);
            *(float2*)&Cout[(m0+8)*384 + col] =
                make_float2(acc[mh][tn][2], acc[mh][tn][3]);
        }
    }
}

// ============================================================
// Fused SSD (R5-exact structure; silu/sigmoid via tanh.approx;
// epilogue emits bf16 hi/lo)
// ============================================================
#define SMX 0
#define SMBT 16896
#define SMCT 25344
#define SMG 33792
#define SMLL 50688
#define SMDT 50944
#define SSD_SMEM_FLOATS 51200
#define SSD_SMEM_BYTES (SSD_SMEM_FLOATS*4)

__global__ __launch_bounds__(512, 1) void ssd_kernel(
    const float* __restrict__ convW, const float* __restrict__ convB,
    const float* __restrict__ Dp, const float* __restrict__ normw, int pf, int pb)
{
    extern __shared__ float sm[];
    int blk = blockIdx.x, dir = blk >> 9, s = blk & 511;
    int pidx = dir ? pb : pf;
    int tid = threadIdx.x;
    const float* zxa = g_zx[dir] + (size_t)s * L_ * 384;

    {
        int ch = tid & 255, hf = tid >> 8;
        float cw0 = convW[pidx*1024 + ch*4 + 0];
        float cw1 = convW[pidx*1024 + ch*4 + 1];
        float cw2 = convW[pidx*1024 + ch*4 + 2];
        float cw3 = convW[pidx*1024 + ch*4 + 3];
        float cb  = convB[pidx*256 + ch];
        const float* src = zxa + 128 + ch;
        float* obase;
        int ostep;
        if (ch < 128)      { obase = sm + SMX + ch;              ostep = 132; }
        else if (ch < 192) { obase = sm + SMBT + (ch-128)*132;   ostep = 1;   }
        else               { obase = sm + SMCT + (ch-192)*132;   ostep = 1;   }
        int ls = hf * 64;
        float xm3 = 0.f, xm2 = 0.f, xm1 = 0.f;
        #pragma unroll
        for (int j = 0; j < 3; j++) {
            int l = ls - 3 + j;
            float v = 0.f;
            if (l >= 0) v = src[(size_t)(dir ? 127-l : l)*384];
            xm3 = xm2; xm2 = xm1; xm1 = v;
        }
        float nxt[4];
        #pragma unroll
        for (int j = 0; j < 4; j++)
            nxt[j] = src[(size_t)(dir ? 127-(ls+j) : (ls+j))*384];
        for (int lb = 0; lb < 64; lb += 4) {
            float cur[4];
            #pragma unroll
            for (int j = 0; j < 4; j++) cur[j] = nxt[j];
            if (lb + 4 < 64) {
                #pragma unroll
                for (int j = 0; j < 4; j++) {
                    int l = ls + lb + 4 + j;
                    nxt[j] = src[(size_t)(dir ? 127-l : l)*384];
                }
            }
            #pragma unroll
            for (int j = 0; j < 4; j++) {
                float v = cur[j];
                float acc = cb;
                acc = fmaf(cw0, xm3, acc);
                acc = fmaf(cw1, xm2, acc);
                acc = fmaf(cw2, xm1, acc);
                acc = fmaf(cw3, v,   acc);
                xm3 = xm2; xm2 = xm1; xm1 = v;
                float y = acc * sigmoid_t(acc);
                obase[(ls + lb + j) * ostep] = y;
            }
        }
    }
    if (tid < 64) {
        int h = tid >> 5, lane = tid & 31;
        float carry = 0.f;
        for (int c = 0; c < 4; c++) {
            int l = c*32 + lane;
            int lp = dir ? 127 - l : l;
            const float* dr = g_dt[dir] + ((size_t)s*128 + lp)*4;
            sm[SMDT + h*128 + l] = dr[h];
            float v = dr[2 + h];
            #pragma unroll
            for (int o = 1; o < 32; o <<= 1) {
                float t = __shfl_up_sync(0xffffffffu, v, o);
                if (lane >= o) v += t;
            }
            sm[SMLL + h*128 + l] = v + carry;
            carry += __shfl_sync(0xffffffffu, v, 31);
        }
    }
    __syncthreads();

    int ti = tid >> 4;
    int pi = tid & 15;
    int t0 = ti * 4;
    float2 accY[2][4][2];
    #pragma unroll
    for (int h = 0; h < 2; h++)
        #pragma unroll
        for (int i = 0; i < 4; i++) {
            accY[h][i][0] = make_float2(0.f, 0.f);
            accY[h][i][1] = make_float2(0.f, 0.f);
        }

    #pragma unroll
    for (int p = 0; p < 2; p++) {
        int s_base = p * 64;
        int s0 = s_base + pi * 4;
        float2 pacc[4][2];
        #pragma unroll
        for (int i = 0; i < 4; i++) {
            pacc[i][0] = make_float2(0.f, 0.f);
            pacc[i][1] = make_float2(0.f, 0.f);
        }
        if (s0 <= t0 + 3) {
            #pragma unroll 4
            for (int n = 0; n < 64; n++) {
                float4 c4 = *(const float4*)&sm[SMCT + n*132 + t0];
                float4 b4 = *(const float4*)&sm[SMBT + n*132 + s0];
                float a[4] = {c4.x, c4.y, c4.z, c4.w};
                float2 bb[2] = {{b4.x, b4.y}, {b4.z, b4.w}};
                #pragma unroll
                for (int i = 0; i < 4; i++) {
                    float2 aa = dup2(a[i]);
                    pacc[i][0] = ffma2(aa, bb[0], pacc[i][0]);
                    pacc[i][1] = ffma2(aa, bb[1], pacc[i][1]);
                }
            }
        }
        #pragma unroll
        for (int h = 0; h < 2; h++) {
            float llt[4];
            #pragma unroll
            for (int i = 0; i < 4; i++) llt[i] = sm[SMLL + h*128 + t0 + i];
            #pragma unroll
            for (int j = 0; j < 4; j++) {
                int sg = s0 + j;
                float dts = sm[SMDT + h*128 + sg];
                float lls = sm[SMLL + h*128 + sg];
                float pv[4];
                #pragma unroll
                for (int i = 0; i < 4; i++)
                    pv[i] = (j & 1) ? pacc[i][j>>1].y : pacc[i][j>>1].x;
                float4 g4;
                g4.x = (sg <= t0+0) ? pv[0]*dts*__expf(llt[0]-lls) : 0.f;
                g4.y = (sg <= t0+1) ? pv[1]*dts*__expf(llt[1]-lls) : 0.f;
                g4.z = (sg <= t0+2) ? pv[2]*dts*__expf(llt[2]-lls) : 0.f;
                g4.w = (sg <= t0+3) ? pv[3]*dts*__expf(llt[3]-lls) : 0.f;
                *(float4*)&sm[SMG + (h*64 + sg - s_base)*132 + t0] = g4;
            }
        }
        __syncthreads();
        int klim = t0 + 4 - s_base;
        if (klim > 64) klim = 64;
        for (int sl = 0; sl < klim; sl++) {
            int sg = s_base + sl;
            float4 g0 = *(const float4*)&sm[SMG + sl*132 + t0];
            float4 g1 = *(const float4*)&sm[SMG + (64 + sl)*132 + t0];
            float4 x0 = *(const float4*)&sm[SMX + sg*132 + pi*4];
            float4 x1 = *(const float4*)&sm[SMX + sg*132 + 64 + pi*4];
            float2 b00 = {x0.x, x0.y}, b01 = {x0.z, x0.w};
            float2 b10 = {x1.x, x1.y}, b11 = {x1.z, x1.w};
            float ga0[4] = {g0.x, g0.y, g0.z, g0.w};
            float ga1[4] = {g1.x, g1.y, g1.z, g1.w};
            #pragma unroll
            for (int i = 0; i < 4; i++) {
                float2 a0 = dup2(ga0[i]);
                float2 a1 = dup2(ga1[i]);
                accY[0][i][0] = ffma2(a0, b00, accY[0][i][0]);
                accY[0][i][1] = ffma2(a0, b01, accY[0][i][1]);
                accY[1][i][0] = ffma2(a1, b10, accY[1][i][0]);
                accY[1][i][1] = ffma2(a1, b11, accY[1][i][1]);
            }
        }
        __syncthreads();
    }

    {
        float Dv0 = Dp[pidx*2], Dv1 = Dp[pidx*2 + 1];
        float4 nw0 = *(const float4*)&normw[pidx*128 + pi*4];
        float4 nw1 = *(const float4*)&normw[pidx*128 + 64 + pi*4];
        #pragma unroll
        for (int i = 0; i < 4; i++) {
            int l = t0 + i;
            int lp = dir ? 127 - l : l;
            float4 x0 = *(const float4*)&sm[SMX + l*132 + pi*4];
            float4 x1 = *(const float4*)&sm[SMX + l*132 + 64 + pi*4];
            const float* zr = zxa + (size_t)lp*384;
            float4 z0 = *(const float4*)&zr[pi*4];
            float4 z1 = *(const float4*)&zr[64 + pi*4];
            float g[8];
            g[0] = fmaf(Dv0, x0.x, accY[0][i][0].x);
            g[1] = fmaf(Dv0, x0.y, accY[0][i][0].y);
            g[2] = fmaf(Dv0, x0.z, accY[0][i][1].x);
            g[3] = fmaf(Dv0, x0.w, accY[0][i][1].y);
            g[4] = fmaf(Dv1, x1.x, accY[1][i][0].x);
            g[5] = fmaf(Dv1, x1.y, accY[1][i][0].y);
            g[6] = fmaf(Dv1, x1.z, accY[1][i][1].x);
            g[7] = fmaf(Dv1, x1.w, accY[1][i][1].y);
            float z[8] = {z0.x, z0.y, z0.z, z0.w, z1.x, z1.y, z1.z, z1.w};
            float ss = 0.f;
            #pragma unroll
            for (int j = 0; j < 8; j++) {
                g[j] = g[j] * (z[j] * sigmoid_t(z[j]));
                ss = fmaf(g[j], g[j], ss);
            }
            ss += __shfl_xor_sync(0xffffffffu, ss, 1);
            ss += __shfl_xor_sync(0xffffffffu, ss, 2);
            ss += __shfl_xor_sync(0xffffffffu, ss, 4);
            ss += __shfl_xor_sync(0xffffffffu, ss, 8);
            float rs = rsqrtf(ss * 0.0078125f + 1e-5f);
            float o0 = g[0]*rs*nw0.x, o1 = g[1]*rs*nw0.y;
            float o2 = g[2]*rs*nw0.z, o3 = g[3]*rs*nw0.w;
            float o4 = g[4]*rs*nw1.x, o5 = g[5]*rs*nw1.y;
            float o6 = g[6]*rs*nw1.z, o7 = g[7]*rs*nw1.w;
            uint32_t* go = g_gb + ((size_t)s*128 + lp)*256;
            int w0 = (dir << 6) + pi*2;
            *(uint2*)&go[w0]          = make_uint2(bfpack(o0, o1), bfpack(o2, o3));
            *(uint2*)&go[w0 + 32]     = make_uint2(bfpack(o4, o5), bfpack(o6, o7));
            *(uint2*)&go[128 + w0]    = make_uint2(bfpack(bfres(o0), bfres(o1)),
                                                   bfpack(bfres(o2), bfres(o3)));
            *(uint2*)&go[128 + w0+32] = make_uint2(bfpack(bfres(o4), bfres(o5)),
                                                   bfpack(bfres(o6), bfres(o7)));
        }
    }
}

// ============================================================
// Fold out_proj x fusion — both stages, packed bf16 hi/lo
// ============================================================
__global__ void wc_all(const float* __restrict__ fW, const float* __restrict__ oW)
{
    int idx = blockIdx.x*256 + threadIdx.x;
    int st = idx >> 14, r = idx & 16383;
    int m = r >> 8, rr = r & 255, dir = rr >> 7, j = rr & 127;
    int pidx = st*2 + dir;
    const float* wo = oW + (size_t)pidx*64*128;
    const float* wf = fW + st*64*128 + m*128 + (dir << 6);
    float acc = 0.f;
    #pragma unroll
    for (int i = 0; i < 64; i++) acc = fmaf(wf[i], wo[i*128 + j], acc);
    float part = __shfl_xor_sync(0xffffffffu, acc, 1);
    if (!(rr & 1)) {
        int kw = rr >> 1;
        uint32_t* o = g_wcb + (size_t)(st*64 + m)*256;
        o[kw]       = bfpack(acc, part);
        o[128 + kw] = bfpack(bfres(acc), bfres(part));
    }
}

// ============================================================
// final GEMM via tensor cores (R14-exact) + residual
// ============================================================
#define GOUT_SMEM_BYTES ((128*132 + 64*132)*4)
__global__ __launch_bounds__(256, 2) void gemm_out_mma(const float* __restrict__ fb,
        const float* __restrict__ x_ext, float* __restrict__ out_ext, int stage)
{
    extern __shared__ uint32_t smo[];
    uint32_t* Asm = smo;
    uint32_t* Bsm = smo + 128*132;
    const float* xin = stage ? g_xwork : x_ext;
    float* xout = stage ? out_ext : g_xwork;
    int blk = blockIdx.x;
    int b = blk >> 7, tt = blk & 127;
    int tid = threadIdx.x;
    int rbase = b*16384 + (stage ? tt : tt*128);
    int rstep = stage ? 128 : 1;

    int wid = tid >> 5, lane = tid & 31;
    int wm = wid & 3, wn = wid >> 2;
    int q = lane >> 2, w = lane & 3;
    uint32_t a_row = (wm*32 + q)*132;
    uint32_t b_row = (wn*32 + q)*132;

    float acc[2][4][4];
    #pragma unroll
    for (int mh = 0; mh < 2; mh++)
        #pragma unroll
        for (int tn = 0; tn < 4; tn++)
            #pragma unroll
            for (int r = 0; r < 4; r++) acc[mh][tn][r] = 0.f;

    for (int half = 0; half < 2; half++) {
        if (half) __syncthreads();
        #pragma unroll
        for (int t = 0; t < 16; t++) {
            int i = tid + t*256;
            int row = i >> 5, wq = i & 31;
            const uint32_t* src = g_gb + (size_t)(rbase + row*rstep)*256;
            int so, dof;
            if (wq < 16) { so = half*64 + wq*4;              dof = wq*4; }
            else         { so = 128 + half*64 + (wq-16)*4;   dof = 64 + (wq-16)*4; }
            *(uint4*)&Asm[row*132 + dof] = *(const uint4*)&src[so];
        }
        #pragma unroll
        for (int t = 0; t < 8; t++) {
            int i = tid + t*256;
            int row = i >> 5, wq = i & 31;
            const uint32_t* src = g_wcb + (size_t)(stage*64 + row)*256;
            int so, dof;
            if (wq < 16) { so = half*64 + wq*4;              dof = wq*4; }
            else         { so = 128 + half*64 + (wq-16)*4;   dof = 64 + (wq-16)*4; }
            *(uint4*)&Bsm[row*132 + dof] = *(const uint4*)&src[so];
        }
        __syncthreads();
        #pragma unroll
        for (int c = 0; c < 3; c++) {
            int aoff = (c == 2) ? 64 : 0;
            int boff = (c == 1) ? 64 : 0;
            #pragma unroll
            for (int kc = 0; kc < 8; kc++) {
                int kb = kc*8 + w;
                uint32_t a0 = Asm[a_row + aoff + kb];
                uint32_t a1 = Asm[a_row + 8*132 + aoff + kb];
                uint32_t a2 = Asm[a_row + aoff + kb + 4];
                uint32_t a3 = Asm[a_row + 8*132 + aoff + kb + 4];
                uint32_t a4 = Asm[a_row + 16*132 + aoff + kb];
                uint32_t a5 = Asm[a_row + 24*132 + aoff + kb];
                uint32_t a6 = Asm[a_row + 16*132 + aoff + kb + 4];
                uint32_t a7 = Asm[a_row + 24*132 + aoff + kb + 4];
                #pragma unroll
                for (int tn = 0; tn < 4; tn++) {
                    uint32_t b0 = Bsm[b_row + tn*8*132 + boff + kb];
                    uint32_t b1 = Bsm[b_row + tn*8*132 + boff + kb + 4];
                    mma16816(acc[0][tn], a0, a1, a2, a3, b0, b1);
                    mma16816(acc[1][tn], a4, a5, a6, a7, b0, b1);
                }
            }
        }
    }
    __syncthreads();
    float* Cs = (float*)smo;
    #pragma unroll
    for (int mh = 0; mh < 2; mh++)
        #pragma unroll
        for (int tn = 0; tn < 4; tn++) {
            int ml = wm*32 + mh*16 + q;
            int col = wn*32 + tn*8 + w*2;
            Cs[col*132 + ml]           = acc[mh][tn][0];
            Cs[(col+1)*132 + ml]       = acc[mh][tn][1];
            Cs[col*132 + ml + 8]       = acc[mh][tn][2];
            Cs[(col+1)*132 + ml + 8]   = acc[mh][tn][3];
        }
    __syncthreads();
    int fq = tid & 31, ng = tid >> 5;
    #pragma unroll
    for (int nn = 0; nn < 8; nn++) {
        int n = ng + nn*8;
        float fbv = fb[n];
        size_t base = (((size_t)(b*64 + n)*128) + tt)*128 + fq*4;
        float4 xv = *(const float4*)&xin[base];
        const float* cr = Cs + n*132 + fq*4;
        float4 o;
        o.x = xv.x + cr[0] + fbv;
        o.y = xv.y + cr[1] + fbv;
        o.z = xv.z + cr[2] + fbv;
        o.w = xv.w + cr[3] + fbv;
        *(float4*)&xout[base] = o;
    }
}

// ============================================================
extern "C" void kernel_launch(void* const* d_in, const int* in_sizes, int n_in,
                              void* d_out, int out_size)
{
    const float* x     = (const float*)d_in[0];
    const float* inW   = (const float*)d_in[1];
    const float* convW = (const float*)d_in[2];
    const float* convB = (const float*)d_in[3];
    const float* dtb   = (const float*)d_in[4];
    const float* Alog  = (const float*)d_in[5];
    const float* Dp    = (const float*)d_in[6];
    const float* nw    = (const float*)d_in[7];
    const float* outW  = (const float*)d_in[8];
    const float* fW    = (const float*)d_in[9];
    const float* fb    = (const float*)d_in[10];
    const float* lnw   = (const float*)d_in[11];
    const float* lnb   = (const float*)d_in[12];
    float* out = (float*)d_out;

    cudaFuncSetAttribute(gemm_in_mma, cudaFuncAttributeMaxDynamicSharedMemorySize,
                         GIN_SMEM_BYTES);
    cudaFuncSetAttribute(ssd_kernel, cudaFuncAttributeMaxDynamicSharedMemorySize,
                         SSD_SMEM_BYTES);
    cudaFuncSetAttribute(gemm_out_mma, cudaFuncAttributeMaxDynamicSharedMemorySize,
                         GOUT_SMEM_BYTES);

    // stage-invariant prep
    w_conv_all<<<96, 256>>>(inW);
    wc_all<<<128, 256>>>(fW, outW);

    for (int st = 0; st < 2; st++) {
        int pf = 2*st, pb = 2*st + 1;
        ln_fused<<<512, 256>>>(x, lnw + st*64, lnb + st*64, inW, dtb, Alog,
                               st, pf, pb);
        gemm_in_mma<<<dim3(6, 512), 256, GIN_SMEM_BYTES>>>(st);
        ssd_kernel<<<1024, 512, SSD_SMEM_BYTES>>>(convW, convB, Dp, nw, pf, pb);
        gemm_out_mma<<<512, 256, GOUT_SMEM_BYTES>>>(fb + st*64, x, out, st);
    }
}

// round 17
// speedup vs baseline: 1.1591x; 1.0346x over previous
#include <cuda_runtime.h>
#include <cuda_bf16.h>
#include <math.h>
#include <stdint.h>

#define S_ 512
#define L_ 128

__device__ __forceinline__ float2 ffma2(float2 a, float2 b, float2 c) {
    unsigned long long ua = *reinterpret_cast<unsigned long long*>(&a);
    unsigned long long ub = *reinterpret_cast<unsigned long long*>(&b);
    unsigned long long uc = *reinterpret_cast<unsigned long long*>(&c);
    unsigned long long ud;
    asm("fma.rn.f32x2 %0, %1, %2, %3;" : "=l"(ud) : "l"(ua), "l"(ub), "l"(uc));
    return *reinterpret_cast<float2*>(&ud);
}
__device__ __forceinline__ float2 dup2(float a) {
    unsigned long long u;
    asm("mov.b64 %0, {%1, %1};" : "=l"(u) : "f"(a));
    return *reinterpret_cast<float2*>(&u);
}
__device__ __forceinline__ uint32_t bfpack(float a, float b) {
    return ((uint32_t)__bfloat16_as_ushort(__float2bfloat16_rn(b)) << 16)
         |  (uint32_t)__bfloat16_as_ushort(__float2bfloat16_rn(a));
}
__device__ __forceinline__ float bfres(float v) {
    return v - __bfloat162float(__float2bfloat16_rn(v));
}
__device__ __forceinline__ float sigmoid_t(float x) {
    float t;
    asm("tanh.approx.f32 %0, %1;" : "=f"(t) : "f"(0.5f * x));
    return fmaf(0.5f, t, 0.5f);
}
__device__ __forceinline__ void mma16816(float* c, uint32_t a0, uint32_t a1,
                                         uint32_t a2, uint32_t a3,
                                         uint32_t b0, uint32_t b1) {
    asm volatile("mma.sync.aligned.m16n8k16.row.col.f32.bf16.bf16.f32 "
        "{%0,%1,%2,%3}, {%4,%5,%6,%7}, {%8,%9}, {%0,%1,%2,%3};"
        : "+f"(c[0]), "+f"(c[1]), "+f"(c[2]), "+f"(c[3])
        : "r"(a0), "r"(a1), "r"(a2), "r"(a3), "r"(b0), "r"(b1));
}

// ---- scratch ----
__device__ __align__(16) float g_xwork[(size_t)4*64*128*128];
__device__ __align__(16) uint32_t g_ub[(size_t)S_*L_*64];   // bf16x2 [row][hi32|lo32]
__device__ __align__(16) uint32_t g_wb[4*384*64];           // all 4 param sets
__device__ __align__(16) float g_zx[2][(size_t)S_*L_*384];
__device__ __align__(16) float g_dt[2][(size_t)S_*L_*4];
__device__ __align__(16) uint32_t g_gb[(size_t)S_*L_*256];  // gated bf16x2 [row][hi128|lo128]
__device__ __align__(16) uint32_t g_wcb[2*64*256];          // folded W bf16x2

// ============================================================
// Fused: LayerNorm + bf16-split pack (-> g_ub) + dt/dA (-> g_dt).
// ============================================================
__global__ __launch_bounds__(256) void ln_fused(const float* __restrict__ x_ext,
        const float* __restrict__ lnw, const float* __restrict__ lnb,
        const float* __restrict__ inW, const float* __restrict__ dtb,
        const float* __restrict__ Alog, int stage, int pf, int pb)
{
    __shared__ float tile[64][133];
    __shared__ float msh[128], rsh[128], wsh[64], bsh[64];
    __shared__ float wsm[2][2][64];
    __shared__ float par[2][2][2];
    const float* xin = stage ? g_xwork : x_ext;
    int bt = blockIdx.x, b = bt >> 7, t = bt & 127;
    int tid = threadIdx.x;
    if (tid < 64) { wsh[tid] = lnw[tid]; bsh[tid] = lnb[tid]; }
    {
        int d = tid >> 7, rest = tid & 127, h = rest >> 6, k = rest & 63;
        int pidx = d ? pb : pf;
        wsm[d][h][k] = inW[(size_t)pidx*386*64 + (384 + h)*64 + k];
    }
    if (tid < 4) {
        int d = tid >> 1, h = tid & 1;
        int pidx = d ? pb : pf;
        par[d][h][0] = dtb[pidx*2 + h];
        par[d][h][1] = -expf(Alog[pidx*2 + h]);
    }
    const float* xb = xin + ((size_t)b*64*128 + t)*128;
    for (int i = tid; i < 8192; i += 256) {
        int c = i >> 7, f = i & 127;
        tile[c][f] = xb[(size_t)c*16384 + f];
    }
    __syncthreads();
    if (tid < 128) {
        float s = 0.f, ss = 0.f;
        #pragma unroll
        for (int c = 0; c < 64; c++) { float v = tile[c][tid]; s += v; ss += v*v; }
        float m = s * 0.015625f;
        msh[tid] = m;
        rsh[tid] = rsqrtf(ss * 0.015625f - m*m + 1e-5f);
    }
    __syncthreads();
    for (int i = tid; i < 8192; i += 256) {
        int c = i >> 7, f = i & 127;
        tile[c][f] = (tile[c][f] - msh[f]) * rsh[f] * wsh[c] + bsh[c];
    }
    __syncthreads();
    {
        int w = tid & 31, fb_ = tid >> 5;
        #pragma unroll
        for (int k = 0; k < 16; k++) {
            int f = fb_ + k*8;
            float a = tile[2*w][f], c2 = tile[2*w + 1][f];
            int row = stage ? ((b << 7) + f)*128 + t : ((b << 7) + t)*128 + f;
            uint32_t* o = g_ub + (size_t)row*64;
            o[w]      = bfpack(a, c2);
            o[32 + w] = bfpack(bfres(a), bfres(c2));
        }
    }
    {
        int f = tid >> 1, d = tid & 1;
        float a0 = 0.f, a1 = 0.f;
        #pragma unroll
        for (int c = 0; c < 64; c++) {
            float v = tile[c][f];
            a0 = fmaf(v, wsm[d][0][c], a0);
            a1 = fmaf(v, wsm[d][1][c], a1);
        }
        float xr0 = a0 + par[d][0][0];
        float xr1 = a1 + par[d][1][0];
        float dt0 = (xr0 > 20.f) ? xr0 : log1pf(expf(xr0));
        float dt1 = (xr1 > 20.f) ? xr1 : log1pf(expf(xr1));
        int row = stage ? ((b << 7) + f)*128 + t : ((b << 7) + t)*128 + f;
        *(float4*)&g_dt[d][(size_t)row*4] =
            make_float4(dt0, dt1, par[d][0][1]*dt0, par[d][1][1]*dt1);
    }
}

// ============================================================
// weight bf16-split conversion, ALL 4 param sets in one launch
// ============================================================
__global__ __launch_bounds__(256) void w_conv_all(const float* __restrict__ inW)
{
    int idx = blockIdx.x*256 + threadIdx.x;
    int p = idx / 6144, r = idx - p*6144;
    int n = r >> 4, wq = r & 15;
    float4 v = *(const float4*)&inW[(size_t)p*386*64 + n*64 + wq*4];
    uint32_t* o = g_wb + (size_t)(p*384 + n)*64;
    int wo = wq*2;
    *(uint2*)&o[wo]      = make_uint2(bfpack(v.x, v.y), bfpack(v.z, v.w));
    *(uint2*)&o[32 + wo] = make_uint2(bfpack(bfres(v.x), bfres(v.y)),
                                      bfpack(bfres(v.z), bfres(v.w)));
}

// ============================================================
// in_proj via tensor cores — 2-pass split: (a_hi + a_lo) * b_hi.
// Weights effectively bf16-rounded; activations split-exact.
// ============================================================
#define GIN_SMEM_BYTES (2*128*68*4)
__global__ __launch_bounds__(256, 2) void gemm_in_mma(int st)
{
    extern __shared__ uint32_t smw[];
    uint32_t* Asm = smw;
    uint32_t* Bsm = smw + 128*68;
    int bx = blockIdx.x;
    int dir = (bx >= 3);
    int j0 = (bx - dir*3) * 128;
    size_t bm = (size_t)blockIdx.y * 128;
    int tid = threadIdx.x;

    const uint4* gu = (const uint4*)&g_ub[bm*64];
    const uint4* gw = (const uint4*)&g_wb[(size_t)((st*2 + dir)*384 + j0)*64];
    #pragma unroll
    for (int t = 0; t < 8; t++) {
        int i = tid + t*256;
        int row = i >> 4, wq = i & 15;
        *(uint4*)&Asm[row*68 + wq*4] = gu[i];
        *(uint4*)&Bsm[row*68 + wq*4] = gw[i];
    }
    __syncthreads();

    int wid = tid >> 5, lane = tid & 31;
    int wm = wid & 3, wn = wid >> 2;
    int q = lane >> 2, w = lane & 3;
    uint32_t a_row = (wm*32 + q)*68;
    uint32_t b_row = (wn*64 + q)*68;

    float acc[2][8][4];
    #pragma unroll
    for (int mh = 0; mh < 2; mh++)
        #pragma unroll
        for (int tn = 0; tn < 8; tn++)
            #pragma unroll
            for (int r = 0; r < 4; r++) acc[mh][tn][r] = 0.f;

    #pragma unroll
    for (int c = 0; c < 2; c++) {
        int aoff = (c == 1) ? 32 : 0;      // pass 0: a_hi * b_hi ; pass 1: a_lo * b_hi
        #pragma unroll
        for (int kc = 0; kc < 4; kc++) {
            int kb = kc*8 + w;
            uint32_t a0 = Asm[a_row + aoff + kb];
            uint32_t a1 = Asm[a_row + 8*68 + aoff + kb];
            uint32_t a2 = Asm[a_row + aoff + kb + 4];
            uint32_t a3 = Asm[a_row + 8*68 + aoff + kb + 4];
            uint32_t a4 = Asm[a_row + 16*68 + aoff + kb];
            uint32_t a5 = Asm[a_row + 24*68 + aoff + kb];
            uint32_t a6 = Asm[a_row + 16*68 + aoff + kb + 4];
            uint32_t a7 = Asm[a_row + 24*68 + aoff + kb + 4];
            #pragma unroll
            for (int tn = 0; tn < 8; tn++) {
                uint32_t b0 = Bsm[b_row + tn*8*68 + kb];
                uint32_t b1 = Bsm[b_row + tn*8*68 + kb + 4];
                mma16816(acc[0][tn], a0, a1, a2, a3, b0, b1);
                mma16816(acc[1][tn], a4, a5, a6, a7, b0, b1);
            }
        }
    }

    float* Cout = g_zx[dir];
    #pragma unroll
    for (int mh = 0; mh < 2; mh++) {
        #pragma unroll
        for (int tn = 0; tn < 8; tn++) {
            size_t m0 = bm + wm*32 + mh*16 + q;
            int col = j0 + wn*64 + tn*8 + w*2;
            *(float2*)&Cout[m0*384 + col] =
                make_float2(acc[mh][tn][0], acc[mh][tn][1]);
            *(float2*)&Cout[(m0+8)*384 + col] =
                make_float2(acc[mh][tn][2], acc[mh][tn][3]);
        }
    }
}

// ============================================================
// Fused SSD (R16-exact)
// ============================================================
#define SMX 0
#define SMBT 16896
#define SMCT 25344
#define SMG 33792
#define SMLL 50688
#define SMDT 50944
#define SSD_SMEM_FLOATS 51200
#define SSD_SMEM_BYTES (SSD_SMEM_FLOATS*4)

__global__ __launch_bounds__(512, 1) void ssd_kernel(
    const float* __restrict__ convW, const float* __restrict__ convB,
    const float* __restrict__ Dp, const float* __restrict__ normw, int pf, int pb)
{
    extern __shared__ float sm[];
    int blk = blockIdx.x, dir = blk >> 9, s = blk & 511;
    int pidx = dir ? pb : pf;
    int tid = threadIdx.x;
    const float* zxa = g_zx[dir] + (size_t)s * L_ * 384;

    {
        int ch = tid & 255, hf = tid >> 8;
        float cw0 = convW[pidx*1024 + ch*4 + 0];
        float cw1 = convW[pidx*1024 + ch*4 + 1];
        float cw2 = convW[pidx*1024 + ch*4 + 2];
        float cw3 = convW[pidx*1024 + ch*4 + 3];
        float cb  = convB[pidx*256 + ch];
        const float* src = zxa + 128 + ch;
        float* obase;
        int ostep;
        if (ch < 128)      { obase = sm + SMX + ch;              ostep = 132; }
        else if (ch < 192) { obase = sm + SMBT + (ch-128)*132;   ostep = 1;   }
        else               { obase = sm + SMCT + (ch-192)*132;   ostep = 1;   }
        int ls = hf * 64;
        float xm3 = 0.f, xm2 = 0.f, xm1 = 0.f;
        #pragma unroll
        for (int j = 0; j < 3; j++) {
            int l = ls - 3 + j;
            float v = 0.f;
            if (l >= 0) v = src[(size_t)(dir ? 127-l : l)*384];
            xm3 = xm2; xm2 = xm1; xm1 = v;
        }
        float nxt[4];
        #pragma unroll
        for (int j = 0; j < 4; j++)
            nxt[j] = src[(size_t)(dir ? 127-(ls+j) : (ls+j))*384];
        for (int lb = 0; lb < 64; lb += 4) {
            float cur[4];
            #pragma unroll
            for (int j = 0; j < 4; j++) cur[j] = nxt[j];
            if (lb + 4 < 64) {
                #pragma unroll
                for (int j = 0; j < 4; j++) {
                    int l = ls + lb + 4 + j;
                    nxt[j] = src[(size_t)(dir ? 127-l : l)*384];
                }
            }
            #pragma unroll
            for (int j = 0; j < 4; j++) {
                float v = cur[j];
                float acc = cb;
                acc = fmaf(cw0, xm3, acc);
                acc = fmaf(cw1, xm2, acc);
                acc = fmaf(cw2, xm1, acc);
                acc = fmaf(cw3, v,   acc);
                xm3 = xm2; xm2 = xm1; xm1 = v;
                float y = acc * sigmoid_t(acc);
                obase[(ls + lb + j) * ostep] = y;
            }
        }
    }
    if (tid < 64) {
        int h = tid >> 5, lane = tid & 31;
        float carry = 0.f;
        for (int c = 0; c < 4; c++) {
            int l = c*32 + lane;
            int lp = dir ? 127 - l : l;
            const float* dr = g_dt[dir] + ((size_t)s*128 + lp)*4;
            sm[SMDT + h*128 + l] = dr[h];
            float v = dr[2 + h];
            #pragma unroll
            for (int o = 1; o < 32; o <<= 1) {
                float t = __shfl_up_sync(0xffffffffu, v, o);
                if (lane >= o) v += t;
            }
            sm[SMLL + h*128 + l] = v + carry;
            carry += __shfl_sync(0xffffffffu, v, 31);
        }
    }
    __syncthreads();

    int ti = tid >> 4;
    int pi = tid & 15;
    int t0 = ti * 4;
    float2 accY[2][4][2];
    #pragma unroll
    for (int h = 0; h < 2; h++)
        #pragma unroll
        for (int i = 0; i < 4; i++) {
            accY[h][i][0] = make_float2(0.f, 0.f);
            accY[h][i][1] = make_float2(0.f, 0.f);
        }

    #pragma unroll
    for (int p = 0; p < 2; p++) {
        int s_base = p * 64;
        int s0 = s_base + pi * 4;
        float2 pacc[4][2];
        #pragma unroll
        for (int i = 0; i < 4; i++) {
            pacc[i][0] = make_float2(0.f, 0.f);
            pacc[i][1] = make_float2(0.f, 0.f);
        }
        if (s0 <= t0 + 3) {
            #pragma unroll 4
            for (int n = 0; n < 64; n++) {
                float4 c4 = *(const float4*)&sm[SMCT + n*132 + t0];
                float4 b4 = *(const float4*)&sm[SMBT + n*132 + s0];
                float a[4] = {c4.x, c4.y, c4.z, c4.w};
                float2 bb[2] = {{b4.x, b4.y}, {b4.z, b4.w}};
                #pragma unroll
                for (int i = 0; i < 4; i++) {
                    float2 aa = dup2(a[i]);
                    pacc[i][0] = ffma2(aa, bb[0], pacc[i][0]);
                    pacc[i][1] = ffma2(aa, bb[1], pacc[i][1]);
                }
            }
        }
        #pragma unroll
        for (int h = 0; h < 2; h++) {
            float llt[4];
            #pragma unroll
            for (int i = 0; i < 4; i++) llt[i] = sm[SMLL + h*128 + t0 + i];
            #pragma unroll
            for (int j = 0; j < 4; j++) {
                int sg = s0 + j;
                float dts = sm[SMDT + h*128 + sg];
                float lls = sm[SMLL + h*128 + sg];
                float pv[4];
                #pragma unroll
                for (int i = 0; i < 4; i++)
                    pv[i] = (j & 1) ? pacc[i][j>>1].y : pacc[i][j>>1].x;
                float4 g4;
                g4.x = (sg <= t0+0) ? pv[0]*dts*__expf(llt[0]-lls) : 0.f;
                g4.y = (sg <= t0+1) ? pv[1]*dts*__expf(llt[1]-lls) : 0.f;
                g4.z = (sg <= t0+2) ? pv[2]*dts*__expf(llt[2]-lls) : 0.f;
                g4.w = (sg <= t0+3) ? pv[3]*dts*__expf(llt[3]-lls) : 0.f;
                *(float4*)&sm[SMG + (h*64 + sg - s_base)*132 + t0] = g4;
            }
        }
        __syncthreads();
        int klim = t0 + 4 - s_base;
        if (klim > 64) klim = 64;
        for (int sl = 0; sl < klim; sl++) {
            int sg = s_base + sl;
            float4 g0 = *(const float4*)&sm[SMG + sl*132 + t0];
            float4 g1 = *(const float4*)&sm[SMG + (64 + sl)*132 + t0];
            float4 x0 = *(const float4*)&sm[SMX + sg*132 + pi*4];
            float4 x1 = *(const float4*)&sm[SMX + sg*132 + 64 + pi*4];
            float2 b00 = {x0.x, x0.y}, b01 = {x0.z, x0.w};
            float2 b10 = {x1.x, x1.y}, b11 = {x1.z, x1.w};
            float ga0[4] = {g0.x, g0.y, g0.z, g0.w};
            float ga1[4] = {g1.x, g1.y, g1.z, g1.w};
            #pragma unroll
            for (int i = 0; i < 4; i++) {
                float2 a0 = dup2(ga0[i]);
                float2 a1 = dup2(ga1[i]);
                accY[0][i][0] = ffma2(a0, b00, accY[0][i][0]);
                accY[0][i][1] = ffma2(a0, b01, accY[0][i][1]);
                accY[1][i][0] = ffma2(a1, b10, accY[1][i][0]);
                accY[1][i][1] = ffma2(a1, b11, accY[1][i][1]);
            }
        }
        __syncthreads();
    }

    {
        float Dv0 = Dp[pidx*2], Dv1 = Dp[pidx*2 + 1];
        float4 nw0 = *(const float4*)&normw[pidx*128 + pi*4];
        float4 nw1 = *(const float4*)&normw[pidx*128 + 64 + pi*4];
        #pragma unroll
        for (int i = 0; i < 4; i++) {
            int l = t0 + i;
            int lp = dir ? 127 - l : l;
            float4 x0 = *(const float4*)&sm[SMX + l*132 + pi*4];
            float4 x1 = *(const float4*)&sm[SMX + l*132 + 64 + pi*4];
            const float* zr = zxa + (size_t)lp*384;
            float4 z0 = *(const float4*)&zr[pi*4];
            float4 z1 = *(const float4*)&zr[64 + pi*4];
            float g[8];
            g[0] = fmaf(Dv0, x0.x, accY[0][i][0].x);
            g[1] = fmaf(Dv0, x0.y, accY[0][i][0].y);
            g[2] = fmaf(Dv0, x0.z, accY[0][i][1].x);
            g[3] = fmaf(Dv0, x0.w, accY[0][i][1].y);
            g[4] = fmaf(Dv1, x1.x, accY[1][i][0].x);
            g[5] = fmaf(Dv1, x1.y, accY[1][i][0].y);
            g[6] = fmaf(Dv1, x1.z, accY[1][i][1].x);
            g[7] = fmaf(Dv1, x1.w, accY[1][i][1].y);
            float z[8] = {z0.x, z0.y, z0.z, z0.w, z1.x, z1.y, z1.z, z1.w};
            float ss = 0.f;
            #pragma unroll
            for (int j = 0; j < 8; j++) {
                g[j] = g[j] * (z[j] * sigmoid_t(z[j]));
                ss = fmaf(g[j], g[j], ss);
            }
            ss += __shfl_xor_sync(0xffffffffu, ss, 1);
            ss += __shfl_xor_sync(0xffffffffu, ss, 2);
            ss += __shfl_xor_sync(0xffffffffu, ss, 4);
            ss += __shfl_xor_sync(0xffffffffu, ss, 8);
            float rs = rsqrtf(ss * 0.0078125f + 1e-5f);
            float o0 = g[0]*rs*nw0.x, o1 = g[1]*rs*nw0.y;
            float o2 = g[2]*rs*nw0.z, o3 = g[3]*rs*nw0.w;
            float o4 = g[4]*rs*nw1.x, o5 = g[5]*rs*nw1.y;
            float o6 = g[6]*rs*nw1.z, o7 = g[7]*rs*nw1.w;
            uint32_t* go = g_gb + ((size_t)s*128 + lp)*256;
            int w0 = (dir << 6) + pi*2;
            *(uint2*)&go[w0]          = make_uint2(bfpack(o0, o1), bfpack(o2, o3));
            *(uint2*)&go[w0 + 32]     = make_uint2(bfpack(o4, o5), bfpack(o6, o7));
            *(uint2*)&go[128 + w0]    = make_uint2(bfpack(bfres(o0), bfres(o1)),
                                                   bfpack(bfres(o2), bfres(o3)));
            *(uint2*)&go[128 + w0+32] = make_uint2(bfpack(bfres(o4), bfres(o5)),
                                                   bfpack(bfres(o6), bfres(o7)));
        }
    }
}

// ============================================================
// Fold out_proj x fusion — both stages, packed bf16 hi/lo
// ============================================================
__global__ void wc_all(const float* __restrict__ fW, const float* __restrict__ oW)
{
    int idx = blockIdx.x*256 + threadIdx.x;
    int st = idx >> 14, r = idx & 16383;
    int m = r >> 8, rr = r & 255, dir = rr >> 7, j = rr & 127;
    int pidx = st*2 + dir;
    const float* wo = oW + (size_t)pidx*64*128;
    const float* wf = fW + st*64*128 + m*128 + (dir << 6);
    float acc = 0.f;
    #pragma unroll
    for (int i = 0; i < 64; i++) acc = fmaf(wf[i], wo[i*128 + j], acc);
    float part = __shfl_xor_sync(0xffffffffu, acc, 1);
    if (!(rr & 1)) {
        int kw = rr >> 1;
        uint32_t* o = g_wcb + (size_t)(st*64 + m)*256;
        o[kw]       = bfpack(acc, part);
        o[128 + kw] = bfpack(bfres(acc), bfres(part));
    }
}

// ============================================================
// final GEMM via tensor cores (R14-exact) + residual
// ============================================================
#define GOUT_SMEM_BYTES ((128*132 + 64*132)*4)
__global__ __launch_bounds__(256, 2) void gemm_out_mma(const float* __restrict__ fb,
        const float* __restrict__ x_ext, float* __restrict__ out_ext, int stage)
{
    extern __shared__ uint32_t smo[];
    uint32_t* Asm = smo;
    uint32_t* Bsm = smo + 128*132;
    const float* xin = stage ? g_xwork : x_ext;
    float* xout = stage ? out_ext : g_xwork;
    int blk = blockIdx.x;
    int b = blk >> 7, tt = blk & 127;
    int tid = threadIdx.x;
    int rbase = b*16384 + (stage ? tt : tt*128);
    int rstep = stage ? 128 : 1;

    int wid = tid >> 5, lane = tid & 31;
    int wm = wid & 3, wn = wid >> 2;
    int q = lane >> 2, w = lane & 3;
    uint32_t a_row = (wm*32 + q)*132;
    uint32_t b_row = (wn*32 + q)*132;

    float acc[2][4][4];
    #pragma unroll
    for (int mh = 0; mh < 2; mh++)
        #pragma unroll
        for (int tn = 0; tn < 4; tn++)
            #pragma unroll
            for (int r = 0; r < 4; r++) acc[mh][tn][r] = 0.f;

    for (int half = 0; half < 2; half++) {
        if (half) __syncthreads();
        #pragma unroll
        for (int t = 0; t < 16; t++) {
            int i = tid + t*256;
            int row = i >> 5, wq = i & 31;
            const uint32_t* src = g_gb + (size_t)(rbase + row*rstep)*256;
            int so, dof;
            if (wq < 16) { so = half*64 + wq*4;              dof = wq*4; }
            else         { so = 128 + half*64 + (wq-16)*4;   dof = 64 + (wq-16)*4; }
            *(uint4*)&Asm[row*132 + dof] = *(const uint4*)&src[so];
        }
        #pragma unroll
        for (int t = 0; t < 8; t++) {
            int i = tid + t*256;
            int row = i >> 5, wq = i & 31;
            const uint32_t* src = g_wcb + (size_t)(stage*64 + row)*256;
            int so, dof;
            if (wq < 16) { so = half*64 + wq*4;              dof = wq*4; }
            else         { so = 128 + half*64 + (wq-16)*4;   dof = 64 + (wq-16)*4; }
            *(uint4*)&Bsm[row*132 + dof] = *(const uint4*)&src[so];
        }
        __syncthreads();
        #pragma unroll
        for (int c = 0; c < 3; c++) {
            int aoff = (c == 2) ? 64 : 0;
            int boff = (c == 1) ? 64 : 0;
            #pragma unroll
            for (int kc = 0; kc < 8; kc++) {
                int kb = kc*8 + w;
                uint32_t a0 = Asm[a_row + aoff + kb];
                uint32_t a1 = Asm[a_row + 8*132 + aoff + kb];
                uint32_t a2 = Asm[a_row + aoff + kb + 4];
                uint32_t a3 = Asm[a_row + 8*132 + aoff + kb + 4];
                uint32_t a4 = Asm[a_row + 16*132 + aoff + kb];
                uint32_t a5 = Asm[a_row + 24*132 + aoff + kb];
                uint32_t a6 = Asm[a_row + 16*132 + aoff + kb + 4];
                uint32_t a7 = Asm[a_row + 24*132 + aoff + kb + 4];
                #pragma unroll
                for (int tn = 0; tn < 4; tn++) {
                    uint32_t b0 = Bsm[b_row + tn*8*132 + boff + kb];
                    uint32_t b1 = Bsm[b_row + tn*8*132 + boff + kb + 4];
                    mma16816(acc[0][tn], a0, a1, a2, a3, b0, b1);
                    mma16816(acc[1][tn], a4, a5, a6, a7, b0, b1);
                }
            }
        }
    }
    __syncthreads();
    float* Cs = (float*)smo;
    #pragma unroll
    for (int mh = 0; mh < 2; mh++)
        #pragma unroll
        for (int tn = 0; tn < 4; tn++) {
            int ml = wm*32 + mh*16 + q;
            int col = wn*32 + tn*8 + w*2;
            Cs[col*132 + ml]           = acc[mh][tn][0];
            Cs[(col+1)*132 + ml]       = acc[mh][tn][1];
            Cs[col*132 + ml + 8]       = acc[mh][tn][2];
            Cs[(col+1)*132 + ml + 8]   = acc[mh][tn][3];
        }
    __syncthreads();
    int fq = tid & 31, ng = tid >> 5;
    #pragma unroll
    for (int nn = 0; nn < 8; nn++) {
        int n = ng + nn*8;
        float fbv = fb[n];
        size_t base = (((size_t)(b*64 + n)*128) + tt)*128 + fq*4;
        float4 xv = *(const float4*)&xin[base];
        const float* cr = Cs + n*132 + fq*4;
        float4 o;
        o.x = xv.x + cr[0] + fbv;
        o.y = xv.y + cr[1] + fbv;
        o.z = xv.z + cr[2] + fbv;
        o.w = xv.w + cr[3] + fbv;
        *(float4*)&xout[base] = o;
    }
}

// ============================================================
extern "C" void kernel_launch(void* const* d_in, const int* in_sizes, int n_in,
                              void* d_out, int out_size)
{
    const float* x     = (const float*)d_in[0];
    const float* inW   = (const float*)d_in[1];
    const float* convW = (const float*)d_in[2];
    const float* convB = (const float*)d_in[3];
    const float* dtb   = (const float*)d_in[4];
    const float* Alog  = (const float*)d_in[5];
    const float* Dp    = (const float*)d_in[6];
    const float* nw    = (const float*)d_in[7];
    const float* outW  = (const float*)d_in[8];
    const float* fW    = (const float*)d_in[9];
    const float* fb    = (const float*)d_in[10];
    const float* lnw   = (const float*)d_in[11];
    const float* lnb   = (const float*)d_in[12];
    float* out = (float*)d_out;

    cudaFuncSetAttribute(gemm_in_mma, cudaFuncAttributeMaxDynamicSharedMemorySize,
                         GIN_SMEM_BYTES);
    cudaFuncSetAttribute(ssd_kernel, cudaFuncAttributeMaxDynamicSharedMemorySize,
                         SSD_SMEM_BYTES);
    cudaFuncSetAttribute(gemm_out_mma, cudaFuncAttributeMaxDynamicSharedMemorySize,
                         GOUT_SMEM_BYTES);

    // stage-invariant prep
    w_conv_all<<<96, 256>>>(inW);
    wc_all<<<128, 256>>>(fW, outW);

    for (int st = 0; st < 2; st++) {
        int pf = 2*st, pb = 2*st + 1;
        ln_fused<<<512, 256>>>(x, lnw + st*64, lnb + st*64, inW, dtb, Alog,
                               st, pf, pb);
        gemm_in_mma<<<dim3(6, 512), 256, GIN_SMEM_BYTES>>>(st);
        ssd_kernel<<<1024, 512, SSD_SMEM_BYTES>>>(convW, convB, Dp, nw, pf, pb);
        gemm_out_mma<<<512, 256, GOUT_SMEM_BYTES>>>(fb + st*64, x, out, st);
    }
}